// round 1
// baseline (speedup 1.0000x reference)
#include <cuda_runtime.h>
#include <cuda_bf16.h>
#include <math.h>

#define Bq 256
#define Sq 10
#define Hq 1024
#define Vq 32000
#define Tq 10

// ---------------- scratch (device globals; no allocation) ----------------
__device__ float g_keysW[Bq * Sq * Hq];
__device__ int   g_tokens[Bq * Tq];
__device__ float g_q[Bq * Hq];
__device__ float g_ctx[Bq * Hq];
__device__ float g_x[Bq * 2 * Hq];
__device__ float g_gi[Bq * 3 * Hq];
__device__ float g_gh[Bq * 3 * Hq];
__device__ float g_h0[Bq * Hq];
__device__ float g_h1[Bq * Hq];
__device__ float g_logits[Bq * Vq];

// ---------------- generic tiled SGEMM: C = A[MxK] * B[NxK]^T + bias ----------------
template <int BM, int BN, int TM, int TN>
__global__ void __launch_bounds__((BM / TM) * (BN / TN))
gemm_bias_kernel(const float* __restrict__ A, const float* __restrict__ Bm,
                 const float* __restrict__ bias, float* __restrict__ C,
                 int M, int N, int K)
{
    constexpr int BK = 16;
    constexpr int THREADS = (BM / TM) * (BN / TN);
    __shared__ float As[BK][BM];
    __shared__ float Bs[BK][BN];

    const int tid  = threadIdx.x;
    const int tcols = BN / TN;
    const int trow = (tid / tcols) * TM;
    const int tcol = (tid % tcols) * TN;
    const int bm = blockIdx.y * BM;
    const int bn = blockIdx.x * BN;

    float acc[TM][TN];
#pragma unroll
    for (int i = 0; i < TM; i++)
#pragma unroll
        for (int j = 0; j < TN; j++) acc[i][j] = 0.f;

    constexpr int A_LD = (BM * BK) / 4 / THREADS; // float4 per thread
    constexpr int B_LD = (BN * BK) / 4 / THREADS;

    for (int k0 = 0; k0 < K; k0 += BK) {
#pragma unroll
        for (int i = 0; i < A_LD; i++) {
            int li = tid + i * THREADS;
            int m  = li / (BK / 4);
            int kk = (li % (BK / 4)) * 4;
            float4 v = *(const float4*)&A[(size_t)(bm + m) * K + k0 + kk];
            As[kk + 0][m] = v.x; As[kk + 1][m] = v.y;
            As[kk + 2][m] = v.z; As[kk + 3][m] = v.w;
        }
#pragma unroll
        for (int i = 0; i < B_LD; i++) {
            int li = tid + i * THREADS;
            int n  = li / (BK / 4);
            int kk = (li % (BK / 4)) * 4;
            float4 v = *(const float4*)&Bm[(size_t)(bn + n) * K + k0 + kk];
            Bs[kk + 0][n] = v.x; Bs[kk + 1][n] = v.y;
            Bs[kk + 2][n] = v.z; Bs[kk + 3][n] = v.w;
        }
        __syncthreads();

#pragma unroll
        for (int k = 0; k < BK; k++) {
            float a[TM], b[TN];
#pragma unroll
            for (int i = 0; i < TM; i += 4) {
                float4 v = *(const float4*)&As[k][trow + i];
                a[i] = v.x; a[i + 1] = v.y; a[i + 2] = v.z; a[i + 3] = v.w;
            }
#pragma unroll
            for (int j = 0; j < TN; j += 4) {
                float4 v = *(const float4*)&Bs[k][tcol + j];
                b[j] = v.x; b[j + 1] = v.y; b[j + 2] = v.z; b[j + 3] = v.w;
            }
#pragma unroll
            for (int i = 0; i < TM; i++)
#pragma unroll
                for (int j = 0; j < TN; j++) acc[i][j] += a[i] * b[j];
        }
        __syncthreads();
    }

#pragma unroll
    for (int i = 0; i < TM; i++) {
#pragma unroll
        for (int j = 0; j < TN; j += 4) {
            float4 v;
            v.x = acc[i][j + 0] + bias[bn + tcol + j + 0];
            v.y = acc[i][j + 1] + bias[bn + tcol + j + 1];
            v.z = acc[i][j + 2] + bias[bn + tcol + j + 2];
            v.w = acc[i][j + 3] + bias[bn + tcol + j + 3];
            *(float4*)&C[(size_t)(bm + trow + i) * N + bn + tcol + j] = v;
        }
    }
}

// ---------------- setup kernels ----------------
__global__ void init_tokens_kernel(const int* __restrict__ target)
{
    int b = threadIdx.x; // 256 threads
    g_tokens[b * Tq + 0] = 0; // SOS
    for (int t = 1; t < Tq; t++) g_tokens[b * Tq + t] = target[b * Tq + t - 1];
}

__global__ void copy_kernel(float* __restrict__ dst, const float* __restrict__ src)
{
    int i = blockIdx.x * blockDim.x + threadIdx.x;
    dst[i] = src[i];
}

// ---------------- attention: score -> softmax -> ctx, per batch row ----------------
__global__ void __launch_bounds__(128)
attn_kernel(const float* __restrict__ q, const float* __restrict__ keys,
            const float* __restrict__ Va, const float* __restrict__ bva,
            float* __restrict__ ctx, float* __restrict__ att_out, int t)
{
    const int b = blockIdx.x;
    const int tid = threadIdx.x;

    float partial[Sq];
#pragma unroll
    for (int s = 0; s < Sq; s++) partial[s] = 0.f;

    for (int h = tid; h < Hq; h += 128) {
        float qv = q[b * Hq + h];
        float va = Va[h];
#pragma unroll
        for (int s = 0; s < Sq; s++) {
            float kw = g_keysW[((size_t)b * Sq + s) * Hq + h];
            partial[s] += va * tanhf(kw + qv);
        }
    }

    __shared__ float red[4][Sq];
    __shared__ float w[Sq];
    int lane = tid & 31, warp = tid >> 5;
#pragma unroll
    for (int s = 0; s < Sq; s++) {
        float v = partial[s];
#pragma unroll
        for (int o = 16; o > 0; o >>= 1) v += __shfl_xor_sync(0xffffffffu, v, o);
        if (lane == 0) red[warp][s] = v;
    }
    __syncthreads();

    if (tid == 0) {
        float sc[Sq];
        float mx = -1e30f;
#pragma unroll
        for (int s = 0; s < Sq; s++) {
            sc[s] = red[0][s] + red[1][s] + red[2][s] + red[3][s] + bva[0];
            mx = fmaxf(mx, sc[s]);
        }
        float sum = 0.f;
#pragma unroll
        for (int s = 0; s < Sq; s++) { sc[s] = expf(sc[s] - mx); sum += sc[s]; }
        float inv = 1.f / sum;
#pragma unroll
        for (int s = 0; s < Sq; s++) w[s] = sc[s] * inv;
    }
    __syncthreads();

    if (tid < Sq) att_out[(size_t)b * (Tq * Sq) + t * Sq + tid] = w[tid];

    for (int h = tid; h < Hq; h += 128) {
        float acc = 0.f;
#pragma unroll
        for (int s = 0; s < Sq; s++)
            acc += w[s] * keys[((size_t)b * Sq + s) * Hq + h];
        ctx[b * Hq + h] = acc;
    }
}

// ---------------- x = [emb[tok], ctx] ----------------
__global__ void build_x_kernel(const float* __restrict__ emb, int t)
{
    int i = blockIdx.x * blockDim.x + threadIdx.x; // B*2H
    int b = i / (2 * Hq);
    int j = i % (2 * Hq);
    float v;
    if (j < Hq) {
        int tok = g_tokens[b * Tq + t];
        v = emb[(size_t)tok * Hq + j];
    } else {
        v = g_ctx[b * Hq + (j - Hq)];
    }
    g_x[i] = v;
}

// ---------------- GRU pointwise ----------------
__global__ void gru_kernel(const float* __restrict__ h, float* __restrict__ hn)
{
    int i = blockIdx.x * blockDim.x + threadIdx.x; // B*H
    int b = i / Hq, j = i % Hq;
    const float* gib = g_gi + (size_t)b * 3 * Hq;
    const float* ghb = g_gh + (size_t)b * 3 * Hq;
    float r = 1.f / (1.f + expf(-(gib[j] + ghb[j])));
    float z = 1.f / (1.f + expf(-(gib[Hq + j] + ghb[Hq + j])));
    float n = tanhf(gib[2 * Hq + j] + r * ghb[2 * Hq + j]);
    hn[i] = (1.f - z) * n + z * h[i];
}

// ---------------- log_softmax over V per row ----------------
__global__ void __launch_bounds__(256)
logsoftmax_kernel(float* __restrict__ out, int t)
{
    const int b = blockIdx.x, tid = threadIdx.x;
    const float* row = g_logits + (size_t)b * Vq;

    float m = -1e30f, s = 0.f;
    for (int v = tid; v < Vq; v += 256) {
        float x = row[v];
        float nm = fmaxf(m, x);
        s = s * expf(m - nm) + expf(x - nm);
        m = nm;
    }
    int lane = tid & 31, warp = tid >> 5;
#pragma unroll
    for (int o = 16; o > 0; o >>= 1) {
        float m2 = __shfl_xor_sync(0xffffffffu, m, o);
        float s2 = __shfl_xor_sync(0xffffffffu, s, o);
        float nm = fmaxf(m, m2);
        s = s * expf(m - nm) + s2 * expf(m2 - nm);
        m = nm;
    }
    __shared__ float sm[8], ss[8];
    __shared__ float lse_sh;
    if (lane == 0) { sm[warp] = m; ss[warp] = s; }
    __syncthreads();
    if (tid == 0) {
        float M = sm[0], S = ss[0];
#pragma unroll
        for (int i = 1; i < 8; i++) {
            float nm = fmaxf(M, sm[i]);
            S = S * expf(M - nm) + ss[i] * expf(sm[i] - nm);
            M = nm;
        }
        lse_sh = M + logf(S);
    }
    __syncthreads();
    float lse = lse_sh;
    float* orow = out + ((size_t)b * Tq + t) * Vq;
    for (int v = tid; v < Vq; v += 256) orow[v] = row[v] - lse;
}

// ---------------- launch ----------------
extern "C" void kernel_launch(void* const* d_in, const int* in_sizes, int n_in,
                              void* d_out, int out_size)
{
    const float* enc_out  = (const float*)d_in[0];  // [B,S,H]
    const float* enc_hid  = (const float*)d_in[1];  // [1,B,H]
    const int*   target   = (const int*)  d_in[2];  // [B,T]
    const float* emb      = (const float*)d_in[3];  // [V,H]
    const float* Wa       = (const float*)d_in[4];
    const float* ba       = (const float*)d_in[5];
    const float* Ua       = (const float*)d_in[6];
    const float* bua      = (const float*)d_in[7];
    const float* Va       = (const float*)d_in[8];
    const float* bva      = (const float*)d_in[9];
    const float* W_ih     = (const float*)d_in[10]; // [3H,2H]
    const float* W_hh     = (const float*)d_in[11]; // [3H,H]
    const float* b_ih     = (const float*)d_in[12];
    const float* b_hh     = (const float*)d_in[13];
    const float* W_out    = (const float*)d_in[14]; // [V,H]
    const float* b_out    = (const float*)d_in[15];

    float* out = (float*)d_out;
    const size_t DEC_OFF = 0;
    const size_t HID_OFF = (size_t)Bq * Tq * Vq;           // 81,920,000
    const size_t ATT_OFF = HID_OFF + (size_t)Bq * Hq;      // +262,144

    float *keysW, *qb, *ctx, *xb, *gi, *gh, *h0, *h1, *logits;
    cudaGetSymbolAddress((void**)&keysW, g_keysW);
    cudaGetSymbolAddress((void**)&qb, g_q);
    cudaGetSymbolAddress((void**)&ctx, g_ctx);
    cudaGetSymbolAddress((void**)&xb, g_x);
    cudaGetSymbolAddress((void**)&gi, g_gi);
    cudaGetSymbolAddress((void**)&gh, g_gh);
    cudaGetSymbolAddress((void**)&h0, g_h0);
    cudaGetSymbolAddress((void**)&h1, g_h1);
    cudaGetSymbolAddress((void**)&logits, g_logits);

    // setup
    init_tokens_kernel<<<1, 256>>>(target);
    copy_kernel<<<(Bq * Hq) / 256, 256>>>(h0, enc_hid); // h_0 = encoder_hidden[0]

    // keysW = keys @ Wa^T + ba   (M = B*S = 2560, N = 1024, K = 1024)
    gemm_bias_kernel<256, 64, 8, 8><<<dim3(Hq / 64, (Bq * Sq) / 256), 256>>>(
        enc_out, Wa, ba, keysW, Bq * Sq, Hq, Hq);

    float* hcur = h0;
    float* hnext = h1;
    for (int t = 0; t < Tq; t++) {
        // q = h @ Ua^T + bua   (256 x 1024 x 1024)
        gemm_bias_kernel<64, 64, 4, 4><<<dim3(Hq / 64, Bq / 64), 256>>>(
            hcur, Ua, bua, qb, Bq, Hq, Hq);

        attn_kernel<<<Bq, 128>>>(qb, enc_out, Va, bva, ctx, out + ATT_OFF, t);

        build_x_kernel<<<(Bq * 2 * Hq) / 256, 256>>>(emb, t);

        // gi = x @ W_ih^T + b_ih  (256 x 3072 x 2048)
        gemm_bias_kernel<64, 64, 4, 4><<<dim3((3 * Hq) / 64, Bq / 64), 256>>>(
            xb, W_ih, b_ih, gi, Bq, 3 * Hq, 2 * Hq);
        // gh = h @ W_hh^T + b_hh  (256 x 3072 x 1024)
        gemm_bias_kernel<64, 64, 4, 4><<<dim3((3 * Hq) / 64, Bq / 64), 256>>>(
            hcur, W_hh, b_hh, gh, Bq, 3 * Hq, Hq);

        gru_kernel<<<(Bq * Hq) / 256, 256>>>(hcur, hnext);

        // logits = h_new @ W_out^T + b_out  (256 x 32000 x 1024)
        gemm_bias_kernel<256, 64, 8, 8><<<dim3(Vq / 64, Bq / 256), 256>>>(
            hnext, W_out, b_out, logits, Bq, Vq, Hq);

        logsoftmax_kernel<<<Bq, 256>>>(out + DEC_OFF, t);

        float* tmp = hcur; hcur = hnext; hnext = tmp;
    }

    // h_last (ends in hcur after final swap)
    copy_kernel<<<(Bq * Hq) / 256, 256>>>(out + HID_OFF, hcur);
}

// round 3
// speedup vs baseline: 2.5896x; 2.5896x over previous
#include <cuda_runtime.h>
#include <cuda_bf16.h>
#include <math.h>
#include <stdint.h>

#define Bq 256
#define Sq 10
#define Hq 1024
#define Vq 32000
#define Tq 10

// ---------------- scratch (device globals; no allocation) ----------------
__device__ float g_keysW[Bq * Sq * Hq];
__device__ int   g_tokens[Bq * Tq];
__device__ float g_q[Bq * Hq];
__device__ float g_ctx[Bq * Hq];
__device__ float g_gi[Bq * 3 * Hq];
__device__ float g_gh[Bq * 3 * Hq];
__device__ float g_h0[Bq * Hq];
__device__ float g_h1[Bq * Hq];
__device__ float g_logits[Bq * Vq];

// bf16 scratch: split-packed (3K layout: [hi | lo | hi] for A, [hi | hi | lo] for W)
__device__ __nv_bfloat16 g_enc2[Bq * Sq * 3 * Hq];       // packed encoder_outputs
__device__ __nv_bfloat16 g_Wa2[Hq * 3 * Hq];
__device__ __nv_bfloat16 g_Ua2[Hq * 3 * Hq];
__device__ __nv_bfloat16 g_Whh2[3 * Hq * 3 * Hq];
__device__ __nv_bfloat16 g_Wih2[3 * Hq * 3 * 2 * Hq];
__device__ __nv_bfloat16 g_h2[Bq * 3 * Hq];              // packed h
__device__ __nv_bfloat16 g_x2[Bq * 3 * 2 * Hq];          // packed x = [emb, ctx]
// plain bf16 for logits path
__device__ __nv_bfloat16 g_Wout_bf[Vq * Hq];
__device__ __nv_bfloat16 g_h_bf[Bq * Hq];

// ---------------- conversion / packing kernels ----------------
__global__ void f2bf_kernel(const float* __restrict__ src, __nv_bfloat16* __restrict__ dst, int n4)
{
    int i = blockIdx.x * blockDim.x + threadIdx.x;
    if (i >= n4) return;
    float4 v = ((const float4*)src)[i];
    __nv_bfloat162 lo = __floats2bfloat162_rn(v.x, v.y);
    __nv_bfloat162 hi = __floats2bfloat162_rn(v.z, v.w);
    uint2 o;
    o.x = *(uint32_t*)&lo;
    o.y = *(uint32_t*)&hi;
    ((uint2*)dst)[i] = o;
}

// Weight pack: dst row has 3K elems: [hi | hi | lo]
__global__ void pack3_w_kernel(const float* __restrict__ src, __nv_bfloat16* __restrict__ dst,
                               int N, int K)
{
    int i = blockIdx.x * blockDim.x + threadIdx.x;
    if (i >= N * K) return;
    int n = i / K, k = i % K;
    float w = src[i];
    __nv_bfloat16 hi = __float2bfloat16(w);
    __nv_bfloat16 lo = __float2bfloat16(w - __bfloat162float(hi));
    __nv_bfloat16* row = dst + (size_t)n * 3 * K;
    row[k] = hi;
    row[K + k] = hi;
    row[2 * K + k] = lo;
}

// Activation pack: dst row has 3K elems: [hi | lo | hi]
__global__ void pack3_a_kernel(const float* __restrict__ src, __nv_bfloat16* __restrict__ dst,
                               int N, int K)
{
    int i = blockIdx.x * blockDim.x + threadIdx.x;
    if (i >= N * K) return;
    int n = i / K, k = i % K;
    float a = src[i];
    __nv_bfloat16 hi = __float2bfloat16(a);
    __nv_bfloat16 lo = __float2bfloat16(a - __bfloat162float(hi));
    __nv_bfloat16* row = dst + (size_t)n * 3 * K;
    row[k] = hi;
    row[K + k] = lo;
    row[2 * K + k] = hi;
}

// ---------------- bf16 tensor-core GEMM: C = A[MxK] * B[NxK]^T + bias ----------------
template <int BM, int BN, int BK, int WM, int WN>
__global__ void __launch_bounds__((BM / WM) * (BN / WN) * 32)
gemm_bf16_bias(const __nv_bfloat16* __restrict__ A, const __nv_bfloat16* __restrict__ B,
               const float* __restrict__ bias, float* __restrict__ C,
               int M, int N, int K)
{
    constexpr int WARPS_M = BM / WM;
    constexpr int WARPS_N = BN / WN;
    constexpr int THREADS = WARPS_M * WARPS_N * 32;
    constexpr int PAD = 8;
    constexpr int LDS_ = BK + PAD;
    constexpr int MI = WM / 16;
    constexpr int NI = WN / 8;

    __shared__ __nv_bfloat16 As[2][BM * LDS_];
    __shared__ __nv_bfloat16 Bs[2][BN * LDS_];

    const int tid = threadIdx.x;
    const int wid = tid / 32, lane = tid % 32;
    const int wm = (wid / WARPS_N) * WM;
    const int wn = (wid % WARPS_N) * WN;
    const int bm = blockIdx.y * BM;
    const int bn = blockIdx.x * BN;

    float acc[MI][NI][4];
#pragma unroll
    for (int i = 0; i < MI; i++)
#pragma unroll
        for (int j = 0; j < NI; j++)
#pragma unroll
            for (int k = 0; k < 4; k++) acc[i][j][k] = 0.f;

    constexpr int A_CH = BM * BK / 8;
    constexpr int B_CH = BN * BK / 8;
    constexpr int CPR = BK / 8;

    const int NK = K / BK;

    {
#pragma unroll
        for (int c = tid; c < A_CH; c += THREADS) {
            int r = c / CPR, cc = (c % CPR) * 8;
            uint32_t sdst = (uint32_t)__cvta_generic_to_shared(&As[0][r * LDS_ + cc]);
            const __nv_bfloat16* src = &A[(size_t)(bm + r) * K + cc];
            asm volatile("cp.async.cg.shared.global [%0], [%1], 16;" :: "r"(sdst), "l"(src));
        }
#pragma unroll
        for (int c = tid; c < B_CH; c += THREADS) {
            int r = c / CPR, cc = (c % CPR) * 8;
            uint32_t sdst = (uint32_t)__cvta_generic_to_shared(&Bs[0][r * LDS_ + cc]);
            const __nv_bfloat16* src = &B[(size_t)(bn + r) * K + cc];
            asm volatile("cp.async.cg.shared.global [%0], [%1], 16;" :: "r"(sdst), "l"(src));
        }
        asm volatile("cp.async.commit_group;");
    }

    const int a_row = lane % 16;
    const int a_col = (lane / 16) * 8;
    const int b_t   = lane & 15;
    const int b_row = b_t % 8;
    const int b_col = (b_t / 8) * 8;

    for (int kt = 0; kt < NK; kt++) {
        int s = kt & 1;
        if (kt + 1 < NK) {
            int ns = (kt + 1) & 1;
            int k0 = (kt + 1) * BK;
#pragma unroll
            for (int c = tid; c < A_CH; c += THREADS) {
                int r = c / CPR, cc = (c % CPR) * 8;
                uint32_t sdst = (uint32_t)__cvta_generic_to_shared(&As[ns][r * LDS_ + cc]);
                const __nv_bfloat16* src = &A[(size_t)(bm + r) * K + k0 + cc];
                asm volatile("cp.async.cg.shared.global [%0], [%1], 16;" :: "r"(sdst), "l"(src));
            }
#pragma unroll
            for (int c = tid; c < B_CH; c += THREADS) {
                int r = c / CPR, cc = (c % CPR) * 8;
                uint32_t sdst = (uint32_t)__cvta_generic_to_shared(&Bs[ns][r * LDS_ + cc]);
                const __nv_bfloat16* src = &B[(size_t)(bn + r) * K + k0 + cc];
                asm volatile("cp.async.cg.shared.global [%0], [%1], 16;" :: "r"(sdst), "l"(src));
            }
            asm volatile("cp.async.commit_group;");
            asm volatile("cp.async.wait_group 1;");
        } else {
            asm volatile("cp.async.wait_group 0;");
        }
        __syncthreads();

#pragma unroll
        for (int kk = 0; kk < BK; kk += 16) {
            uint32_t af[MI][4];
#pragma unroll
            for (int mi = 0; mi < MI; mi++) {
                uint32_t addr = (uint32_t)__cvta_generic_to_shared(
                    &As[s][(wm + mi * 16 + a_row) * LDS_ + kk + a_col]);
                asm volatile("ldmatrix.sync.aligned.m8n8.x4.shared.b16 {%0,%1,%2,%3}, [%4];"
                             : "=r"(af[mi][0]), "=r"(af[mi][1]), "=r"(af[mi][2]), "=r"(af[mi][3])
                             : "r"(addr));
            }
            uint32_t bf[NI][2];
#pragma unroll
            for (int ni = 0; ni < NI; ni++) {
                uint32_t addr = (uint32_t)__cvta_generic_to_shared(
                    &Bs[s][(wn + ni * 8 + b_row) * LDS_ + kk + b_col]);
                asm volatile("ldmatrix.sync.aligned.m8n8.x2.shared.b16 {%0,%1}, [%2];"
                             : "=r"(bf[ni][0]), "=r"(bf[ni][1])
                             : "r"(addr));
            }
#pragma unroll
            for (int mi = 0; mi < MI; mi++) {
#pragma unroll
                for (int ni = 0; ni < NI; ni++) {
                    asm volatile(
                        "mma.sync.aligned.m16n8k16.row.col.f32.bf16.bf16.f32 "
                        "{%0,%1,%2,%3}, {%4,%5,%6,%7}, {%8,%9}, {%0,%1,%2,%3};"
                        : "+f"(acc[mi][ni][0]), "+f"(acc[mi][ni][1]),
                          "+f"(acc[mi][ni][2]), "+f"(acc[mi][ni][3])
                        : "r"(af[mi][0]), "r"(af[mi][1]), "r"(af[mi][2]), "r"(af[mi][3]),
                          "r"(bf[ni][0]), "r"(bf[ni][1]));
                }
            }
        }
        __syncthreads();
    }

#pragma unroll
    for (int mi = 0; mi < MI; mi++) {
        int row0 = bm + wm + mi * 16 + lane / 4;
#pragma unroll
        for (int ni = 0; ni < NI; ni++) {
            int col = bn + wn + ni * 8 + 2 * (lane % 4);
            float2 bv = *(const float2*)&bias[col];
            float2 v0 = make_float2(acc[mi][ni][0] + bv.x, acc[mi][ni][1] + bv.y);
            float2 v1 = make_float2(acc[mi][ni][2] + bv.x, acc[mi][ni][3] + bv.y);
            *(float2*)&C[(size_t)row0 * N + col] = v0;
            *(float2*)&C[(size_t)(row0 + 8) * N + col] = v1;
        }
    }
}

// ---------------- setup kernels ----------------
__global__ void init_tokens_kernel(const int* __restrict__ target)
{
    int b = threadIdx.x;
    g_tokens[b * Tq + 0] = 0; // SOS
    for (int t = 1; t < Tq; t++) g_tokens[b * Tq + t] = target[b * Tq + t - 1];
}

// h0: copy fp32 + pack split + plain bf16
__global__ void copy_h0_kernel(float* __restrict__ dst, const float* __restrict__ src)
{
    int i = blockIdx.x * blockDim.x + threadIdx.x; // B*H
    int b = i / Hq, j = i % Hq;
    float v = src[i];
    dst[i] = v;
    g_h_bf[i] = __float2bfloat16(v);
    __nv_bfloat16 hi = __float2bfloat16(v);
    __nv_bfloat16 lo = __float2bfloat16(v - __bfloat162float(hi));
    __nv_bfloat16* row = g_h2 + (size_t)b * 3 * Hq;
    row[j] = hi; row[Hq + j] = lo; row[2 * Hq + j] = hi;
}

__global__ void copy_kernel(float* __restrict__ dst, const float* __restrict__ src)
{
    int i = blockIdx.x * blockDim.x + threadIdx.x;
    dst[i] = src[i];
}

// ---------------- attention ----------------
__global__ void __launch_bounds__(128)
attn_kernel(const float* __restrict__ q, const float* __restrict__ keys,
            const float* __restrict__ Va, const float* __restrict__ bva,
            float* __restrict__ ctx, float* __restrict__ att_out, int t)
{
    const int b = blockIdx.x;
    const int tid = threadIdx.x;

    float partial[Sq];
#pragma unroll
    for (int s = 0; s < Sq; s++) partial[s] = 0.f;

    for (int h = tid; h < Hq; h += 128) {
        float qv = q[b * Hq + h];
        float va = Va[h];
#pragma unroll
        for (int s = 0; s < Sq; s++) {
            float kw = g_keysW[((size_t)b * Sq + s) * Hq + h];
            partial[s] += va * tanhf(kw + qv);
        }
    }

    __shared__ float red[4][Sq];
    __shared__ float w[Sq];
    int lane = tid & 31, warp = tid >> 5;
#pragma unroll
    for (int s = 0; s < Sq; s++) {
        float v = partial[s];
#pragma unroll
        for (int o = 16; o > 0; o >>= 1) v += __shfl_xor_sync(0xffffffffu, v, o);
        if (lane == 0) red[warp][s] = v;
    }
    __syncthreads();

    if (tid == 0) {
        float sc[Sq];
        float mx = -1e30f;
#pragma unroll
        for (int s = 0; s < Sq; s++) {
            sc[s] = red[0][s] + red[1][s] + red[2][s] + red[3][s] + bva[0];
            mx = fmaxf(mx, sc[s]);
        }
        float sum = 0.f;
#pragma unroll
        for (int s = 0; s < Sq; s++) { sc[s] = expf(sc[s] - mx); sum += sc[s]; }
        float inv = 1.f / sum;
#pragma unroll
        for (int s = 0; s < Sq; s++) w[s] = sc[s] * inv;
    }
    __syncthreads();

    if (tid < Sq) att_out[(size_t)b * (Tq * Sq) + t * Sq + tid] = w[tid];

    for (int h = tid; h < Hq; h += 128) {
        float acc = 0.f;
#pragma unroll
        for (int s = 0; s < Sq; s++)
            acc += w[s] * keys[((size_t)b * Sq + s) * Hq + h];
        ctx[b * Hq + h] = acc;
    }
}

// ---------------- x = [emb[tok], ctx], packed split (row = 6H: [hi|lo|hi]) ----------------
__global__ void build_x3_kernel(const float* __restrict__ emb, int t)
{
    int i = blockIdx.x * blockDim.x + threadIdx.x; // B*2H
    int b = i / (2 * Hq);
    int j = i % (2 * Hq);
    float v;
    if (j < Hq) {
        int tok = g_tokens[b * Tq + t];
        v = emb[(size_t)tok * Hq + j];
    } else {
        v = g_ctx[b * Hq + (j - Hq)];
    }
    __nv_bfloat16 hi = __float2bfloat16(v);
    __nv_bfloat16 lo = __float2bfloat16(v - __bfloat162float(hi));
    __nv_bfloat16* row = g_x2 + (size_t)b * 6 * Hq;
    row[j] = hi; row[2 * Hq + j] = lo; row[4 * Hq + j] = hi;
}

// ---------------- GRU pointwise: fp32 state + split pack + plain bf16 ----------------
__global__ void gru_kernel(const float* __restrict__ h, float* __restrict__ hn)
{
    int i = blockIdx.x * blockDim.x + threadIdx.x; // B*H
    int b = i / Hq, j = i % Hq;
    const float* gib = g_gi + (size_t)b * 3 * Hq;
    const float* ghb = g_gh + (size_t)b * 3 * Hq;
    float r = 1.f / (1.f + expf(-(gib[j] + ghb[j])));
    float z = 1.f / (1.f + expf(-(gib[Hq + j] + ghb[Hq + j])));
    float n = tanhf(gib[2 * Hq + j] + r * ghb[2 * Hq + j]);
    float hv = (1.f - z) * n + z * h[i];
    hn[i] = hv;
    g_h_bf[i] = __float2bfloat16(hv);
    __nv_bfloat16 hi = __float2bfloat16(hv);
    __nv_bfloat16 lo = __float2bfloat16(hv - __bfloat162float(hi));
    __nv_bfloat16* row = g_h2 + (size_t)b * 3 * Hq;
    row[j] = hi; row[Hq + j] = lo; row[2 * Hq + j] = hi;
}

// ---------------- log_softmax over V per row ----------------
__global__ void __launch_bounds__(256)
logsoftmax_kernel(float* __restrict__ out, int t)
{
    const int b = blockIdx.x, tid = threadIdx.x;
    const float* row = g_logits + (size_t)b * Vq;

    float m = -1e30f, s = 0.f;
    for (int v = tid; v < Vq; v += 256) {
        float x = row[v];
        float nm = fmaxf(m, x);
        s = s * expf(m - nm) + expf(x - nm);
        m = nm;
    }
    int lane = tid & 31, warp = tid >> 5;
#pragma unroll
    for (int o = 16; o > 0; o >>= 1) {
        float m2 = __shfl_xor_sync(0xffffffffu, m, o);
        float s2 = __shfl_xor_sync(0xffffffffu, s, o);
        float nm = fmaxf(m, m2);
        s = s * expf(m - nm) + s2 * expf(m2 - nm);
        m = nm;
    }
    __shared__ float sm[8], ss[8];
    __shared__ float lse_sh;
    if (lane == 0) { sm[warp] = m; ss[warp] = s; }
    __syncthreads();
    if (tid == 0) {
        float M = sm[0], S = ss[0];
#pragma unroll
        for (int i = 1; i < 8; i++) {
            float nm = fmaxf(M, sm[i]);
            S = S * expf(M - nm) + ss[i] * expf(sm[i] - nm);
            M = nm;
        }
        lse_sh = M + logf(S);
    }
    __syncthreads();
    float lse = lse_sh;
    float* orow = out + ((size_t)b * Tq + t) * Vq;
    for (int v = tid; v < Vq; v += 256) orow[v] = row[v] - lse;
}

// ---------------- launch ----------------
extern "C" void kernel_launch(void* const* d_in, const int* in_sizes, int n_in,
                              void* d_out, int out_size)
{
    const float* enc_out  = (const float*)d_in[0];
    const float* enc_hid  = (const float*)d_in[1];
    const int*   target   = (const int*)  d_in[2];
    const float* emb      = (const float*)d_in[3];
    const float* Wa       = (const float*)d_in[4];
    const float* ba       = (const float*)d_in[5];
    const float* Ua       = (const float*)d_in[6];
    const float* bua      = (const float*)d_in[7];
    const float* Va       = (const float*)d_in[8];
    const float* bva      = (const float*)d_in[9];
    const float* W_ih     = (const float*)d_in[10];
    const float* W_hh     = (const float*)d_in[11];
    const float* b_ih     = (const float*)d_in[12];
    const float* b_hh     = (const float*)d_in[13];
    const float* W_out    = (const float*)d_in[14];
    const float* b_out    = (const float*)d_in[15];

    float* out = (float*)d_out;
    const size_t HID_OFF = (size_t)Bq * Tq * Vq;
    const size_t ATT_OFF = HID_OFF + (size_t)Bq * Hq;

    float *keysW, *qb, *ctx, *gi, *gh, *h0, *h1, *logits;
    __nv_bfloat16 *enc2, *Wa2, *Ua2, *Whh2, *Wih2, *h2, *x2, *Wout_bf, *h_bf;
    cudaGetSymbolAddress((void**)&keysW, g_keysW);
    cudaGetSymbolAddress((void**)&qb, g_q);
    cudaGetSymbolAddress((void**)&ctx, g_ctx);
    cudaGetSymbolAddress((void**)&gi, g_gi);
    cudaGetSymbolAddress((void**)&gh, g_gh);
    cudaGetSymbolAddress((void**)&h0, g_h0);
    cudaGetSymbolAddress((void**)&h1, g_h1);
    cudaGetSymbolAddress((void**)&logits, g_logits);
    cudaGetSymbolAddress((void**)&enc2, g_enc2);
    cudaGetSymbolAddress((void**)&Wa2, g_Wa2);
    cudaGetSymbolAddress((void**)&Ua2, g_Ua2);
    cudaGetSymbolAddress((void**)&Whh2, g_Whh2);
    cudaGetSymbolAddress((void**)&Wih2, g_Wih2);
    cudaGetSymbolAddress((void**)&h2, g_h2);
    cudaGetSymbolAddress((void**)&x2, g_x2);
    cudaGetSymbolAddress((void**)&Wout_bf, g_Wout_bf);
    cudaGetSymbolAddress((void**)&h_bf, g_h_bf);

    // setup
    init_tokens_kernel<<<1, 256>>>(target);
    copy_h0_kernel<<<(Bq * Hq) / 256, 256>>>(h0, enc_hid);

    // one-time weight conversions
    f2bf_kernel<<<(Vq * Hq / 4 + 255) / 256, 256>>>(W_out, Wout_bf, Vq * Hq / 4);
    pack3_w_kernel<<<(Hq * Hq + 255) / 256, 256>>>(Wa, Wa2, Hq, Hq);
    pack3_w_kernel<<<(Hq * Hq + 255) / 256, 256>>>(Ua, Ua2, Hq, Hq);
    pack3_w_kernel<<<(3 * Hq * Hq + 255) / 256, 256>>>(W_hh, Whh2, 3 * Hq, Hq);
    pack3_w_kernel<<<(3 * Hq * 2 * Hq + 255) / 256, 256>>>(W_ih, Wih2, 3 * Hq, 2 * Hq);
    pack3_a_kernel<<<(Bq * Sq * Hq + 255) / 256, 256>>>(enc_out, enc2, Bq * Sq, Hq);

    // keysW = keys @ Wa^T + ba  (split bf16: M=2560, N=1024, K=3072)
    gemm_bf16_bias<128, 128, 32, 64, 32><<<dim3(Hq / 128, (Bq * Sq) / 128), 256>>>(
        enc2, Wa2, ba, keysW, Bq * Sq, Hq, 3 * Hq);

    float* hcur = h0;
    float* hnext = h1;
    for (int t = 0; t < Tq; t++) {
        // q = h @ Ua^T + bua  (split, K=3072)
        gemm_bf16_bias<64, 64, 32, 32, 32><<<dim3(Hq / 64, Bq / 64), 128>>>(
            h2, Ua2, bua, qb, Bq, Hq, 3 * Hq);

        attn_kernel<<<Bq, 128>>>(qb, enc_out, Va, bva, ctx, out + ATT_OFF, t);

        build_x3_kernel<<<(Bq * 2 * Hq) / 256, 256>>>(emb, t);

        // gi = x @ W_ih^T + b_ih  (split, K=6144)
        gemm_bf16_bias<64, 64, 32, 32, 32><<<dim3((3 * Hq) / 64, Bq / 64), 128>>>(
            x2, Wih2, b_ih, gi, Bq, 3 * Hq, 6 * Hq);
        // gh = h @ W_hh^T + b_hh  (split, K=3072)
        gemm_bf16_bias<64, 64, 32, 32, 32><<<dim3((3 * Hq) / 64, Bq / 64), 128>>>(
            h2, Whh2, b_hh, gh, Bq, 3 * Hq, 3 * Hq);

        gru_kernel<<<(Bq * Hq) / 256, 256>>>(hcur, hnext);

        // logits = h_new @ W_out^T + b_out  (plain bf16, K=1024)
        gemm_bf16_bias<128, 128, 32, 64, 32><<<dim3(Vq / 128, Bq / 128), 256>>>(
            h_bf, Wout_bf, b_out, logits, Bq, Vq, Hq);

        logsoftmax_kernel<<<Bq, 256>>>(out, t);

        float* tmp = hcur; hcur = hnext; hnext = tmp;
    }

    copy_kernel<<<(Bq * Hq) / 256, 256>>>(out + HID_OFF, hcur);
}